// round 1
// baseline (speedup 1.0000x reference)
#include <cuda_runtime.h>

#define S_LEN 4096
#define D_DIM 1024
#define BATCH 4
#define TOK   (BATCH * S_LEN)   // 16384

// scratch for q, k, v projections (allocation-free rule -> __device__ global)
__device__ float g_qkv[(size_t)3 * TOK * D_DIM];

// ---------------------------------------------------------------------------
// Projection GEMM: out[z] = X @ W[z] + b[z], z in {q,k,v}
// 128x128 tile, K-chunks of 8, double buffered, 256 threads, 8x8 micro-tile
// ---------------------------------------------------------------------------
__global__ __launch_bounds__(256, 2)
void proj_kernel(const float* __restrict__ X,
                 const float* __restrict__ Wq, const float* __restrict__ bq,
                 const float* __restrict__ Wk, const float* __restrict__ bk,
                 const float* __restrict__ Wv, const float* __restrict__ bv)
{
    const int z = blockIdx.z;
    const float* W    = (z == 0) ? Wq : (z == 1) ? Wk : Wv;
    const float* bias = (z == 0) ? bq : (z == 1) ? bk : bv;
    float* out = g_qkv + (size_t)z * TOK * D_DIM;

    const int m0 = blockIdx.y * 128;
    const int n0 = blockIdx.x * 128;

    __shared__ float As[2][8][128];   // [buf][k][m]
    __shared__ float Bs[2][8][128];   // [buf][k][n]

    const int t    = threadIdx.x;
    const int arow = t >> 1;            // 0..127
    const int ac   = (t & 1) * 4;       // 0 or 4
    const int brow = t >> 5;            // 0..7
    const int bc   = (t & 31) * 4;      // 0..124
    const int tx   = t & 15;
    const int ty   = t >> 4;

    const float* Ap = X + (size_t)(m0 + arow) * D_DIM + ac;
    const float* Bp = W + (size_t)brow * D_DIM + n0 + bc;

    float acc[8][8];
#pragma unroll
    for (int i = 0; i < 8; ++i)
#pragma unroll
        for (int j = 0; j < 8; ++j) acc[i][j] = 0.f;

    // prologue: tile 0
    {
        float4 ra = *(const float4*)Ap;
        float4 rb = *(const float4*)Bp;
        As[0][ac + 0][arow] = ra.x;
        As[0][ac + 1][arow] = ra.y;
        As[0][ac + 2][arow] = ra.z;
        As[0][ac + 3][arow] = ra.w;
        *(float4*)&Bs[0][brow][bc] = rb;
    }
    __syncthreads();

    const int NT = D_DIM / 8;           // 128
    for (int kt = 0; kt < NT; ++kt) {
        const int buf = kt & 1;
        float4 na, nb;
        if (kt + 1 < NT) {
            na = *(const float4*)(Ap + (kt + 1) * 8);
            nb = *(const float4*)(Bp + (size_t)(kt + 1) * 8 * D_DIM);
        }
#pragma unroll
        for (int k = 0; k < 8; ++k) {
            float a[8], b[8];
            *(float4*)&a[0] = *(const float4*)&As[buf][k][ty * 4];
            *(float4*)&a[4] = *(const float4*)&As[buf][k][64 + ty * 4];
            *(float4*)&b[0] = *(const float4*)&Bs[buf][k][tx * 4];
            *(float4*)&b[4] = *(const float4*)&Bs[buf][k][64 + tx * 4];
#pragma unroll
            for (int i = 0; i < 8; ++i)
#pragma unroll
                for (int j = 0; j < 8; ++j)
                    acc[i][j] += a[i] * b[j];
        }
        if (kt + 1 < NT) {
            const int nbuf = buf ^ 1;
            As[nbuf][ac + 0][arow] = na.x;
            As[nbuf][ac + 1][arow] = na.y;
            As[nbuf][ac + 2][arow] = na.z;
            As[nbuf][ac + 3][arow] = na.w;
            *(float4*)&Bs[nbuf][brow][bc] = nb;
            __syncthreads();
        }
    }

    // epilogue: add bias, store
#pragma unroll
    for (int ii = 0; ii < 2; ++ii)
#pragma unroll
        for (int i = 0; i < 4; ++i) {
            const int row = m0 + ii * 64 + ty * 4 + i;
#pragma unroll
            for (int jj = 0; jj < 2; ++jj) {
                const int col = n0 + jj * 64 + tx * 4;
                float4 r;
                r.x = acc[ii * 4 + i][jj * 4 + 0] + bias[col + 0];
                r.y = acc[ii * 4 + i][jj * 4 + 1] + bias[col + 1];
                r.z = acc[ii * 4 + i][jj * 4 + 2] + bias[col + 2];
                r.w = acc[ii * 4 + i][jj * 4 + 3] + bias[col + 3];
                *(float4*)&out[(size_t)row * D_DIM + col] = r;
            }
        }
}

// ---------------------------------------------------------------------------
// Flash attention: M=32 queries/CTA, key chunks of 64, d staged in 128-chunks
// 512 threads. O accumulator register-resident (64 floats/thread).
// ---------------------------------------------------------------------------
#define KV_PITCH 132
#define PS_PITCH 66
#define SM_FLOATS (32 * 1024 + 64 * KV_PITCH + 32 * PS_PITCH + 32 + 32 + 32 + 64 + 64)

__global__ __launch_bounds__(512, 1)
void attn_kernel(float* __restrict__ out)
{
    extern __shared__ float sm[];
    float* Qs   = sm;                     // [32][1024]
    float* KVs  = Qs + 32 * 1024;         // [64][132]
    float* Ps   = KVs + 64 * KV_PITCH;    // [32][66]
    float* m_s  = Ps + 32 * PS_PITCH;     // [32]
    float* l_s  = m_s + 32;               // [32]
    float* al_s = l_s + 32;               // [32]
    float* redm = al_s + 32;              // [16][4]
    float* reds = redm + 64;              // [16][4]

    const int t     = threadIdx.x;
    const int b     = blockIdx.y;
    const int qbase = blockIdx.x * 32;

    const float* qg = g_qkv + (size_t)b * S_LEN * D_DIM + (size_t)qbase * D_DIM;
    const float* kg = g_qkv + (size_t)TOK * D_DIM     + (size_t)b * S_LEN * D_DIM;
    const float* vg = g_qkv + (size_t)2 * TOK * D_DIM + (size_t)b * S_LEN * D_DIM;

    // stage Q tile (32 x 1024)
#pragma unroll
    for (int i = 0; i < 16; ++i) {
        const int idx = t + i * 512;       // float4 index, 8192 total
        const int row = idx >> 8;
        const int c4  = idx & 255;
        *(float4*)&Qs[row * 1024 + c4 * 4] =
            *(const float4*)(qg + (size_t)row * D_DIM + c4 * 4);
    }
    if (t < 32) { m_s[t] = -1e30f; l_s[t] = 0.f; }

    const int c    = t & 63;     // key col within chunk (S phase)
    const int rq   = t >> 6;     // row group 0..7 (S phase: rows rq+8i)
    const int rp   = t >> 4;     // row 0..31 (PV phase)
    const int cg   = t & 15;     // col group (PV phase)
    const int lane = t & 31;
    const int w    = t >> 5;

    float o[64];
#pragma unroll
    for (int i = 0; i < 64; ++i) o[i] = 0.f;

    const int kcmax = (qbase + 31) >> 6;
    for (int kc = 0; kc <= kcmax; ++kc) {
        const int j0 = kc << 6;

        // ---- phase 1: S = Q K^T over full d=1024, staged 128 at a time ----
        float s[4] = {0.f, 0.f, 0.f, 0.f};
        for (int dc = 0; dc < 8; ++dc) {
            __syncthreads();   // prior KVs use complete
#pragma unroll
            for (int i = 0; i < 4; ++i) {
                const int idx = t + i * 512;   // 2048 float4
                const int row = idx >> 5;
                const int c4  = idx & 31;
                *(float4*)&KVs[row * KV_PITCH + c4 * 4] =
                    *(const float4*)(kg + (size_t)(j0 + row) * D_DIM + dc * 128 + c4 * 4);
            }
            __syncthreads();
            const float* Kr = &KVs[c * KV_PITCH];
            const float* Q0 = &Qs[(rq + 0)  * 1024 + dc * 128];
            const float* Q1 = &Qs[(rq + 8)  * 1024 + dc * 128];
            const float* Q2 = &Qs[(rq + 16) * 1024 + dc * 128];
            const float* Q3 = &Qs[(rq + 24) * 1024 + dc * 128];
#pragma unroll 4
            for (int d4 = 0; d4 < 32; ++d4) {
                const float4 kv = *(const float4*)(Kr + d4 * 4);
                float4 q;
                q = *(const float4*)(Q0 + d4 * 4);
                s[0] += q.x * kv.x + q.y * kv.y + q.z * kv.z + q.w * kv.w;
                q = *(const float4*)(Q1 + d4 * 4);
                s[1] += q.x * kv.x + q.y * kv.y + q.z * kv.z + q.w * kv.w;
                q = *(const float4*)(Q2 + d4 * 4);
                s[2] += q.x * kv.x + q.y * kv.y + q.z * kv.z + q.w * kv.w;
                q = *(const float4*)(Q3 + d4 * 4);
                s[3] += q.x * kv.x + q.y * kv.y + q.z * kv.z + q.w * kv.w;
            }
        }

        // ---- scale + causal mask ----
#pragma unroll
        for (int i2 = 0; i2 < 4; ++i2) {
            const int qr = qbase + rq + 8 * i2;
            s[i2] = ((j0 + c) <= qr) ? s[i2] * 0.03125f : -1e30f;
        }

        // ---- online softmax bookkeeping ----
        float mx[4] = {s[0], s[1], s[2], s[3]};
#pragma unroll
        for (int off = 16; off; off >>= 1) {
#pragma unroll
            for (int i2 = 0; i2 < 4; ++i2)
                mx[i2] = fmaxf(mx[i2], __shfl_xor_sync(0xffffffffu, mx[i2], off));
        }
        if (lane == 0) {
#pragma unroll
            for (int i2 = 0; i2 < 4; ++i2) redm[w * 4 + i2] = mx[i2];
        }
        __syncthreads();
        if (t < 32) {
            const int r  = t;
            const int rr = r & 7;
            const int ii = r >> 3;
            const float rowmax = fmaxf(redm[(2 * rr) * 4 + ii], redm[(2 * rr + 1) * 4 + ii]);
            const float mo = m_s[r];
            const float mn = fmaxf(mo, rowmax);
            m_s[r]  = mn;
            al_s[r] = __expf(mo - mn);
        }
        __syncthreads();

        float p[4], ps[4];
#pragma unroll
        for (int i2 = 0; i2 < 4; ++i2) {
            const int r = rq + 8 * i2;
            p[i2] = __expf(s[i2] - m_s[r]);   // masked s=-1e30 -> exp underflows to 0
            Ps[r * PS_PITCH + c] = p[i2];
            ps[i2] = p[i2];
        }
#pragma unroll
        for (int off = 16; off; off >>= 1) {
#pragma unroll
            for (int i2 = 0; i2 < 4; ++i2)
                ps[i2] += __shfl_xor_sync(0xffffffffu, ps[i2], off);
        }
        if (lane == 0) {
#pragma unroll
            for (int i2 = 0; i2 < 4; ++i2) reds[w * 4 + i2] = ps[i2];
        }
        __syncthreads();
        if (t < 32) {
            const int r  = t;
            const int rr = r & 7;
            const int ii = r >> 3;
            const float rsum = reds[(2 * rr) * 4 + ii] + reds[(2 * rr + 1) * 4 + ii];
            l_s[r] = l_s[r] * al_s[r] + rsum;
        }

        // ---- rescale O by alpha ----
        const float alpha = al_s[rp];
#pragma unroll
        for (int i = 0; i < 64; ++i) o[i] *= alpha;

        // ---- phase 2: O += P @ V, d staged 128 at a time ----
#pragma unroll
        for (int dc = 0; dc < 8; ++dc) {
            __syncthreads();   // prior KVs use complete (incl. reds read above)
#pragma unroll
            for (int i = 0; i < 4; ++i) {
                const int idx = t + i * 512;
                const int row = idx >> 5;
                const int c4  = idx & 31;
                *(float4*)&KVs[row * KV_PITCH + c4 * 4] =
                    *(const float4*)(vg + (size_t)(j0 + row) * D_DIM + dc * 128 + c4 * 4);
            }
            __syncthreads();
            const float* Pr = &Ps[rp * PS_PITCH];
#pragma unroll 2
            for (int j = 0; j < 64; ++j) {
                const float pv = Pr[j];
#pragma unroll
                for (int i2 = 0; i2 < 4; ++i2) {
                    const float2 vv = *(const float2*)&KVs[j * KV_PITCH + 32 * i2 + 2 * cg];
                    o[dc * 8 + 2 * i2 + 0] += pv * vv.x;
                    o[dc * 8 + 2 * i2 + 1] += pv * vv.y;
                }
            }
        }
    }

    // ---- epilogue: normalize and store ----
    const float inv = 1.0f / l_s[rp];
    float* og = out + (size_t)b * S_LEN * D_DIM + (size_t)(qbase + rp) * D_DIM;
#pragma unroll
    for (int dc = 0; dc < 8; ++dc)
#pragma unroll
        for (int i2 = 0; i2 < 4; ++i2) {
            float2 vv;
            vv.x = o[dc * 8 + 2 * i2 + 0] * inv;
            vv.y = o[dc * 8 + 2 * i2 + 1] * inv;
            *(float2*)&og[dc * 128 + 32 * i2 + 2 * cg] = vv;
        }
}

// ---------------------------------------------------------------------------
extern "C" void kernel_launch(void* const* d_in, const int* in_sizes, int n_in,
                              void* d_out, int out_size)
{
    const float* x  = (const float*)d_in[0];
    const float* Wq = (const float*)d_in[1];
    const float* bq = (const float*)d_in[2];
    const float* Wk = (const float*)d_in[3];
    const float* bk = (const float*)d_in[4];
    const float* Wv = (const float*)d_in[5];
    const float* bv = (const float*)d_in[6];
    float* out = (float*)d_out;

    dim3 pg(D_DIM / 128, TOK / 128, 3);
    proj_kernel<<<pg, 256>>>(x, Wq, bq, Wk, bk, Wv, bv);

    const size_t attn_smem = (size_t)SM_FLOATS * sizeof(float);   // 174208 B
    cudaFuncSetAttribute(attn_kernel, cudaFuncAttributeMaxDynamicSharedMemorySize,
                         (int)attn_smem);
    dim3 ag(S_LEN / 32, BATCH);
    attn_kernel<<<ag, 512, attn_smem>>>(out);
}